// round 1
// baseline (speedup 1.0000x reference)
#include <cuda_runtime.h>
#include <math.h>

#define DDIM 512
#define KC 8192
#define TOPK_ 8
#define TM 128
#define TN 128
#define DK 16
#define SQRTD 22.627416997969522f
#define NMAX 32768

// scratch (no allocations allowed)
__device__ float g_qnorm[NMAX];
__device__ float g_cnorm[KC];

// packed fp32x2 FMA — Blackwell dual-rate fp32 pipe, only reachable via PTX
#define FMA2(acc, a, b) asm("fma.rn.f32x2 %0, %1, %2, %0;" : "+l"(acc) : "l"(a), "l"(b))

__global__ void qnorm_kernel(const float* __restrict__ q, int nrows) {
    int row = blockIdx.x * 8 + (threadIdx.x >> 5);
    if (row >= nrows) return;
    int lane = threadIdx.x & 31;
    const float4* p = (const float4*)(q + (size_t)row * DDIM);
    float s = 0.f;
#pragma unroll
    for (int k = 0; k < 4; ++k) {
        float4 v = p[lane + k * 32];
        s += v.x * v.x + v.y * v.y + v.z * v.z + v.w * v.w;
    }
#pragma unroll
    for (int off = 16; off; off >>= 1) s += __shfl_xor_sync(0xffffffffu, s, off);
    if (lane == 0) g_qnorm[row] = s;
}

__global__ void cnorm_kernel(const float* __restrict__ codebook, const int* __restrict__ midx) {
    int m = midx ? midx[0] : 0;
    const float* cb = codebook + (size_t)m * KC * DDIM;
    int row = blockIdx.x * 8 + (threadIdx.x >> 5);
    if (row >= KC) return;
    int lane = threadIdx.x & 31;
    const float4* p = (const float4*)(cb + (size_t)row * DDIM);
    float s = 0.f;
#pragma unroll
    for (int k = 0; k < 4; ++k) {
        float4 v = p[lane + k * 32];
        s += v.x * v.x + v.y * v.y + v.z * v.z + v.w * v.w;
    }
#pragma unroll
    for (int off = 16; off; off >>= 1) s += __shfl_xor_sync(0xffffffffu, s, off);
    if (lane == 0) g_cnorm[row] = s;
}

// replace current min of an 8-entry list, recompute min. Rare slow path.
__device__ __forceinline__ void insert8(float* lv, int* li, float& rmin, float s, int c) {
    int am = 0; float mv = lv[0];
#pragma unroll
    for (int j = 1; j < 8; ++j) if (lv[j] < mv) { mv = lv[j]; am = j; }
    lv[am] = s; li[am] = c;
    mv = lv[0];
#pragma unroll
    for (int j = 1; j < 8; ++j) mv = fminf(mv, lv[j]);
    rmin = mv;
}

__global__ __launch_bounds__(256)
void main_kernel(const float* __restrict__ q,
                 const float* __restrict__ comp,
                 const float* __restrict__ codebook,
                 const float* __restrict__ log_temp,
                 const int* __restrict__ midx,
                 float* __restrict__ out_ret,
                 float* __restrict__ out_w,
                 int T) {
    // A tile stored duplicated ({a,a} float2) so f32x2 operands load directly.
    // Pads chosen for conflict-free STS (see strides: 130*8B, 132*4B) and 16B
    // alignment of the vector LDS in the main loop.
    __shared__ __align__(16) float2 As[DK][TM + 2];   // [d][row] dup pairs
    __shared__ __align__(16) float  Bs[DK][TN + 4];   // [d][code]
    __shared__ float s_cn[TN];
    __shared__ float s_topv[TM][TOPK_];
    __shared__ int   s_topi[TM][TOPK_];
    __shared__ float s_w[TM][TOPK_];

    const int tid = threadIdx.x;
    const int tx = tid & 15;        // code group: cols tx*8 .. tx*8+7
    const int ty = tid >> 4;        // row group:  rows ty*8 .. ty*8+7
    const int m = midx ? midx[0] : 0;
    const float* cb = codebook + (size_t)m * KC * DDIM;
    const int rowbase = blockIdx.x * TM;

    unsigned long long acc[8][4];
    float lv[8][TOPK_]; int li[8][TOPK_];
    float rmin[8];
#pragma unroll
    for (int r = 0; r < 8; ++r) {
        rmin[r] = -INFINITY;
#pragma unroll
        for (int k = 0; k < TOPK_; ++k) { lv[r][k] = -INFINITY; li[r][k] = -1; }
    }

    const int arow = tid >> 1;            // 0..127
    const int adh  = (tid & 1) * 8;       // 0 or 8
    const float* aptr = q + (size_t)(rowbase + arow) * DDIM + adh;
    const int bcode = tid >> 1;
    const int bdh   = (tid & 1) * 8;

    for (int ct = 0; ct < KC / TN; ++ct) {
        const int code0 = ct * TN;
#pragma unroll
        for (int r = 0; r < 8; ++r)
#pragma unroll
            for (int p = 0; p < 4; ++p) acc[r][p] = 0ull;

        __syncthreads();                       // protect s_cn vs previous epilogue
        if (tid < TN) s_cn[tid] = g_cnorm[code0 + tid];

        for (int d0 = 0; d0 < DDIM; d0 += DK) {
            // global loads first (start early)
            float4 a0 = *(const float4*)(aptr + d0);
            float4 a1 = *(const float4*)(aptr + d0 + 4);
            const float* bp = cb + (size_t)(code0 + bcode) * DDIM + d0 + bdh;
            float4 b0 = *(const float4*)(bp);
            float4 b1 = *(const float4*)(bp + 4);
            __syncthreads();                   // previous compute done reading smem
            As[adh + 0][arow] = make_float2(a0.x, a0.x);
            As[adh + 1][arow] = make_float2(a0.y, a0.y);
            As[adh + 2][arow] = make_float2(a0.z, a0.z);
            As[adh + 3][arow] = make_float2(a0.w, a0.w);
            As[adh + 4][arow] = make_float2(a1.x, a1.x);
            As[adh + 5][arow] = make_float2(a1.y, a1.y);
            As[adh + 6][arow] = make_float2(a1.z, a1.z);
            As[adh + 7][arow] = make_float2(a1.w, a1.w);
            Bs[bdh + 0][bcode] = b0.x;
            Bs[bdh + 1][bcode] = b0.y;
            Bs[bdh + 2][bcode] = b0.z;
            Bs[bdh + 3][bcode] = b0.w;
            Bs[bdh + 4][bcode] = b1.x;
            Bs[bdh + 5][bcode] = b1.y;
            Bs[bdh + 6][bcode] = b1.z;
            Bs[bdh + 7][bcode] = b1.w;
            __syncthreads();
#pragma unroll
            for (int d = 0; d < DK; ++d) {
                ulonglong2 b01 = *(const ulonglong2*)&Bs[d][tx * 8];
                ulonglong2 b23 = *(const ulonglong2*)&Bs[d][tx * 8 + 4];
#pragma unroll
                for (int rr = 0; rr < 4; ++rr) {
                    ulonglong2 aa = *(const ulonglong2*)&As[d][ty * 8 + rr * 2];
                    FMA2(acc[rr * 2][0], aa.x, b01.x);
                    FMA2(acc[rr * 2][1], aa.x, b01.y);
                    FMA2(acc[rr * 2][2], aa.x, b23.x);
                    FMA2(acc[rr * 2][3], aa.x, b23.y);
                    FMA2(acc[rr * 2 + 1][0], aa.y, b01.x);
                    FMA2(acc[rr * 2 + 1][1], aa.y, b01.y);
                    FMA2(acc[rr * 2 + 1][2], aa.y, b23.x);
                    FMA2(acc[rr * 2 + 1][3], aa.y, b23.y);
                }
            }
        }

        // epilogue: rank by s' = 2*dot - ||c||^2 (monotone in sim per row)
#pragma unroll
        for (int r = 0; r < 8; ++r) {
#pragma unroll
            for (int p = 0; p < 4; ++p) {
                unsigned long long v = acc[r][p];
                float dlo = __uint_as_float((unsigned)v);
                float dhi = __uint_as_float((unsigned)(v >> 32));
                int cl = tx * 8 + p * 2;
                float s0 = fmaf(2.f, dlo, -s_cn[cl]);
                float s1 = fmaf(2.f, dhi, -s_cn[cl + 1]);
                if (s0 > rmin[r]) insert8(lv[r], li[r], rmin[r], s0, code0 + cl);
                if (s1 > rmin[r]) insert8(lv[r], li[r], rmin[r], s1, code0 + cl + 1);
            }
        }
    }

    __syncthreads();
    // merge: for each row, 16 lanes (half-warp, width-16 shuffles) each hold a
    // top-8 partial list; extract global top-8 in descending order.
    for (int r = 0; r < 8; ++r) {
        for (int k = 0; k < TOPK_; ++k) {
            float bv = lv[r][0]; int bs = 0;
#pragma unroll
            for (int j = 1; j < 8; ++j) if (lv[r][j] > bv) { bv = lv[r][j]; bs = j; }
            int bi = li[r][bs];
#pragma unroll
            for (int off = 8; off >= 1; off >>= 1) {
                float ov = __shfl_xor_sync(0xffffffffu, bv, off, 16);
                int   oi = __shfl_xor_sync(0xffffffffu, bi, off, 16);
                if (ov > bv || (ov == bv && (unsigned)oi < (unsigned)bi)) { bv = ov; bi = oi; }
            }
            // owner removes (code indices are unique across lanes)
            if (li[r][bs] == bi) { lv[r][bs] = -INFINITY; li[r][bs] = -1; }
            if (tx == 0) { s_topv[ty * 8 + r][k] = bv; s_topi[ty * 8 + r][k] = bi; }
        }
    }
    __syncthreads();

    // softmax with adaptive temperature + weight scatter (one thread per row)
    if (tid < TM) {
        int grow = rowbase + tid;
        float qn = g_qnorm[grow];
        int b = grow / T;
        float at = expf(log_temp[0]) * (2.0f - comp[b]);
        float l[TOPK_];
#pragma unroll
        for (int k = 0; k < TOPK_; ++k) {
            float sim = (s_topv[tid][k] - qn) / SQRTD;  // == -(qn+cn-2dot)/sqrt(D)
            l[k] = sim / at;
        }
        float mx = l[0];                                // entries are descending
        float sum = 0.f;
#pragma unroll
        for (int k = 0; k < TOPK_; ++k) { l[k] = expf(l[k] - mx); sum += l[k]; }
#pragma unroll
        for (int k = 0; k < TOPK_; ++k) {
            float w = l[k] / sum;
            s_w[tid][k] = w;
            out_w[(size_t)grow * KC + s_topi[tid][k]] = w;
        }
    }
    __syncthreads();

    // retrieved = sum_k w_k * cb[idx_k]  (cooperative: 2 dims per thread)
    const int dim = tid * 2;
    for (int rl = 0; rl < TM; ++rl) {
        int grow = rowbase + rl;
        float r0 = 0.f, r1 = 0.f;
#pragma unroll
        for (int k = 0; k < TOPK_; ++k) {
            float w = s_w[rl][k];
            float2 v = *(const float2*)(cb + (size_t)s_topi[rl][k] * DDIM + dim);
            r0 = fmaf(w, v.x, r0);
            r1 = fmaf(w, v.y, r1);
        }
        *(float2*)(out_ret + (size_t)grow * DDIM + dim) = make_float2(r0, r1);
    }
}

extern "C" void kernel_launch(void* const* d_in, const int* in_sizes, int n_in,
                              void* d_out, int out_size) {
    const float* q     = (const float*)d_in[0];
    const float* comp  = (const float*)d_in[1];
    const float* cbook = (const float*)d_in[2];
    const float* ltemp = (const float*)d_in[3];
    const int*   midx  = (n_in > 4) ? (const int*)d_in[4] : nullptr;
    // d_in[5] (top_k) is compile-time 8 here

    int N = in_sizes[0] / DDIM;
    int B = in_sizes[1];
    int T = N / B;

    float* out_ret = (float*)d_out;
    float* out_w   = out_ret + (size_t)N * DDIM;

    // zero the sparse weights output (poisoned to 0xAA by harness)
    cudaMemsetAsync(out_w, 0, (size_t)N * KC * sizeof(float));

    qnorm_kernel<<<(N + 7) / 8, 256>>>(q, N);
    cnorm_kernel<<<KC / 8, 256>>>(cbook, midx);
    main_kernel<<<N / TM, 256>>>(q, comp, cbook, ltemp, midx, out_ret, out_w, T);
}